// round 16
// baseline (speedup 1.0000x reference)
#include <cuda_runtime.h>

// ---------------------------------------------------------------------------
// SDGNN forward. N=100000, D=64, E=1e6, L=2, R=4.
// R13 config (fused gemm_all, 16-lane serial gather, dual-stream CSR overlap)
// + FFMA-dense MLP: 256 thr, 8 rows x 2 cols per thread, warp-broadcast
// activations (64 FFMA : 16 LDS per k-step -> FMA-pipe bound).
// ---------------------------------------------------------------------------

#define MAXN 100000
#define MAXE 1000000
#define DD   64
#define TOT  (4 * MAXN)
#define NB1  ((TOT + 1023) / 1024)

__device__ __align__(16) float g_x2[(size_t)MAXN * DD];       // inter-layer act
__device__ __align__(16) float g_h [(size_t)4 * MAXN * DD];   // h[r] = x @ Wg[l,r]
__device__ __align__(16) float g_gat[(size_t)MAXN * 4 * DD];  // [row][r*64+c]
__device__ __align__(16) int2  g_e[(size_t)4 * MAXE];         // packed edges
__device__ int   g_eidx[(size_t)4 * MAXE];                    // CSR src indices
__device__ int   g_hist[TOT];
__device__ int   g_scan[TOT];
__device__ int   g_rp[TOT + 1];
__device__ int   g_cur[TOT];
__device__ int   g_bsum[NB1];
__device__ int   g_boff[NB1];
__device__ float g_as[(size_t)4 * MAXN];
__device__ float g_ad[(size_t)4 * MAXN];
__device__ float g_was[256];
__device__ float g_wad[256];
__device__ int   g_ms[4];
__device__ int   g_md[4];
__device__ int   g_is64;

// ---------------------------------------------------------------------------
__global__ void detect_kernel(const unsigned int* __restrict__ e) {
    __shared__ int any;
    if (threadIdx.x == 0) any = 0;
    __syncthreads();
    int i = 1 + 2 * threadIdx.x;
    if (i < 512 && e[i] != 0u) atomicOr(&any, 1);
    __syncthreads();
    if (threadIdx.x == 0) g_is64 = any ? 0 : 1;
}

__global__ void zero_hist_kernel() {
    int i = blockIdx.x * blockDim.x + threadIdx.x;
    if (i < TOT) g_hist[i] = 0;
}

__global__ void hist_kernel(const void* __restrict__ edges, long long E, int R) {
    long long i = (long long)blockIdx.x * blockDim.x + threadIdx.x;
    long long tot = (long long)R * E;
    if (i >= tot) return;
    int r = (int)(i / E);
    long long j = i - (long long)r * E;
    int s, d;
    if (g_is64) {
        const long long* p = (const long long*)edges;
        s = (int)p[(long long)(2 * r) * E + j];
        d = (int)p[(long long)(2 * r + 1) * E + j];
    } else {
        const int* p = (const int*)edges;
        s = p[(long long)(2 * r) * E + j];
        d = p[(long long)(2 * r + 1) * E + j];
    }
    g_e[(size_t)r * MAXE + j] = make_int2(s, d);
    atomicAdd(&g_hist[r * MAXN + d], 1);
}

// ---------------------------------------------------------------------------
__global__ void scan1_kernel() {
    __shared__ int sbuf[2][256];
    int t = threadIdx.x;
    int b = blockIdx.x;
    int base = b * 1024 + t * 4;
    int v0 = (base + 0 < TOT) ? g_hist[base + 0] : 0;
    int v1 = (base + 1 < TOT) ? g_hist[base + 1] : 0;
    int v2 = (base + 2 < TOT) ? g_hist[base + 2] : 0;
    int v3 = (base + 3 < TOT) ? g_hist[base + 3] : 0;
    int p0 = v0, p1 = p0 + v1, p2 = p1 + v2, p3 = p2 + v3;

    int cur = 0;
    sbuf[0][t] = p3;
    __syncthreads();
    for (int off = 1; off < 256; off <<= 1) {
        int v = sbuf[cur][t];
        if (t >= off) v += sbuf[cur][t - off];
        sbuf[1 - cur][t] = v;
        cur = 1 - cur;
        __syncthreads();
    }
    int incl = sbuf[cur][t];
    int offset = incl - p3;
    if (base + 0 < TOT) g_scan[base + 0] = offset + p0;
    if (base + 1 < TOT) g_scan[base + 1] = offset + p1;
    if (base + 2 < TOT) g_scan[base + 2] = offset + p2;
    if (base + 3 < TOT) g_scan[base + 3] = offset + p3;
    if (t == 255) g_bsum[b] = incl;
}

__global__ void scan2_kernel() {
    __shared__ int sbuf[2][512];
    int t = threadIdx.x;
    int v = (t < NB1) ? g_bsum[t] : 0;
    int cur = 0;
    sbuf[0][t] = v;
    __syncthreads();
    for (int off = 1; off < 512; off <<= 1) {
        int x = sbuf[cur][t];
        if (t >= off) x += sbuf[cur][t - off];
        sbuf[1 - cur][t] = x;
        cur = 1 - cur;
        __syncthreads();
    }
    if (t < NB1) g_boff[t] = sbuf[cur][t] - v;
}

__global__ void scan3_kernel() {
    int i = blockIdx.x * blockDim.x + threadIdx.x;
    if (i >= TOT) return;
    int incl = g_scan[i] + g_boff[i >> 10];
    g_rp[i + 1] = incl;
    g_cur[i] = incl - g_hist[i];
    if (i == 0) g_rp[0] = 0;
}

__global__ void scatter_kernel(long long E, int R) {
    long long i = (long long)blockIdx.x * blockDim.x + threadIdx.x;
    long long tot = (long long)R * E;
    if (i >= tot) return;
    int r = (int)(i / E);
    long long j = i - (long long)r * E;
    int2 e2 = g_e[(size_t)r * MAXE + j];
    int pos = atomicAdd(&g_cur[r * MAXN + e2.y], 1);
    g_eidx[pos] = e2.x;
}

// ---------------------------------------------------------------------------
__device__ __forceinline__ void atomic_fmax(int* addr, float v) {
    if (v >= 0.f) atomicMax(addr, __float_as_int(v));
    else          atomicMin((unsigned int*)addr, __float_as_uint(v));
}
__device__ __forceinline__ unsigned fkey(float f) {
    unsigned u = __float_as_uint(f);
    return (u & 0x80000000u) ? ~u : (u | 0x80000000u);
}
__device__ __forceinline__ float funkey(unsigned k) {
    unsigned u = (k & 0x80000000u) ? (k ^ 0x80000000u) : ~k;
    return __uint_as_float(u);
}

// ---------------------------------------------------------------------------
__global__ void wa_kernel(const float* __restrict__ Wg_l,
                          const float* __restrict__ as_l,
                          const float* __restrict__ ad_l) {
    int t = threadIdx.x;
    int rel = t >> 6, k = t & 63;
    const float* Wrow = Wg_l + (size_t)rel * DD * DD + (size_t)k * DD;
    float accs = 0.f, accd = 0.f;
#pragma unroll 8
    for (int c = 0; c < DD; c++) {
        float wv = Wrow[c];
        accs += wv * as_l[rel * DD + c];
        accd += wv * ad_l[rel * DD + c];
    }
    g_was[t] = accs;
    g_wad[t] = accd;
    if (t < 4) { g_ms[t] = 0xff800000; g_md[t] = 0xff800000; }
}

// ---------------------------------------------------------------------------
__global__ void alpha_kernel(int src_sel, const float* __restrict__ xin, int n) {
    const float* xsrc = src_sel ? g_x2 : xin;
    __shared__ float ws[512];
    __shared__ unsigned smax[8];
    int t = threadIdx.x;
    for (int i = t; i < 512; i += 256) {
        int o = i >> 6, k = i & 63;
        ws[i] = (o & 1) ? g_wad[(o >> 1) * 64 + k] : g_was[(o >> 1) * 64 + k];
    }
    if (t < 8) smax[t] = 0u;
    __syncthreads();

    unsigned lmax[8];
#pragma unroll
    for (int o = 0; o < 8; o++) lmax[o] = 0u;

    for (long long node = (long long)blockIdx.x * 256 + t; node < n;
         node += (long long)gridDim.x * 256) {
        float4 xr[16];
        const float4* xp = (const float4*)xsrc + (size_t)node * 16;
#pragma unroll
        for (int k4 = 0; k4 < 16; k4++) xr[k4] = xp[k4];
#pragma unroll
        for (int o = 0; o < 8; o++) {
            const float4* wv = (const float4*)(ws + o * 64);
            float acc = 0.f;
#pragma unroll
            for (int k4 = 0; k4 < 16; k4++) {
                float4 w4 = wv[k4];
                float4 x4 = xr[k4];
                acc += x4.x * w4.x + x4.y * w4.y + x4.z * w4.z + x4.w * w4.w;
            }
            int r = o >> 1;
            if (o & 1) g_ad[(size_t)r * MAXN + node] = acc;
            else       g_as[(size_t)r * MAXN + node] = acc;
            unsigned k = fkey(acc);
            if (k > lmax[o]) lmax[o] = k;
        }
    }
#pragma unroll
    for (int o = 0; o < 8; o++) atomicMax(&smax[o], lmax[o]);
    __syncthreads();
    if (t < 8) {
        float v = funkey(smax[t]);
        if (t & 1) atomic_fmax(&g_md[t >> 1], v);
        else       atomic_fmax(&g_ms[t >> 1], v);
    }
}

// ---------------------------------------------------------------------------
// Pure fused 4-relation GEMM: h[r] = x @ Wg[l,r]. (R13-proven)
// ---------------------------------------------------------------------------
__global__ void gemm_all_kernel(int src_sel, const float* __restrict__ xin,
                                const float* __restrict__ Wg_l, int n) {
    const float* xsrc = src_sel ? g_x2 : xin;
    __shared__ float4 xs[256];
    int t   = threadIdx.x;
    int col = t & 63;
    int rel = t >> 6;

    float w[DD];
    const float* Wr = Wg_l + (size_t)rel * DD * DD;
#pragma unroll
    for (int k = 0; k < DD; k++) w[k] = Wr[k * DD + col];

    for (long long base = (long long)blockIdx.x * 16; base < n;
         base += (long long)gridDim.x * 16) {
        __syncthreads();
        {
            int lr = t >> 4, lc = t & 15;
            if (base + lr < n)
                xs[t] = ((const float4*)xsrc)[(size_t)(base + lr) * 16 + lc];
        }
        __syncthreads();
        int rows = (n - base < 16) ? (int)(n - base) : 16;
        for (int q = 0; q < rows; q++) {
            float acc = 0.f;
            const float4* xv4 = xs + q * 16;
#pragma unroll
            for (int k4 = 0; k4 < 16; k4++) {
                float4 xv = xv4[k4];
                acc += xv.x * w[4 * k4 + 0] + xv.y * w[4 * k4 + 1] +
                       xv.z * w[4 * k4 + 2] + xv.w * w[4 * k4 + 3];
            }
            g_h[((size_t)rel * MAXN + base + q) * DD + col] = acc;
        }
    }
}

// ---------------------------------------------------------------------------
// CSR gather, serial per-dst loop (R13-proven): grid (ceil(n/16), 4).
// ---------------------------------------------------------------------------
__global__ void gather_kernel(const float* __restrict__ bg_l, int n) {
    int r    = blockIdx.y;
    int grp  = threadIdx.x >> 4;
    int lane = threadIdx.x & 15;
    int d = blockIdx.x * 16 + grp;
    if (d >= n) return;

    size_t rb = (size_t)r * MAXN;
    float mg = fmaxf(__int_as_float(g_ms[r]) + __int_as_float(g_md[r]), 0.f);
    float ad_d = g_ad[rb + d];
    const float4* h4 = (const float4*)g_h;
    const float* asp = g_as;

    float e = asp[rb + d] + ad_d;
    e = e > 0.f ? e : 0.2f * e;
    float wv = __expf(e - mg);
    float den = wv;
    float4 hv = h4[(rb + d) * 16 + lane];
    float4 acc = make_float4(hv.x * wv, hv.y * wv, hv.z * wv, hv.w * wv);

    int start = g_rp[r * MAXN + d];
    int end   = g_rp[r * MAXN + d + 1];
    for (int j = start; j < end; j++) {
        int s = g_eidx[j];
        float es = asp[rb + s] + ad_d;
        es = es > 0.f ? es : 0.2f * es;
        float ww = __expf(es - mg);
        den += ww;
        float4 hs = h4[(rb + s) * 16 + lane];
        acc.x += hs.x * ww; acc.y += hs.y * ww;
        acc.z += hs.z * ww; acc.w += hs.w * ww;
    }

    float rd = __fdividef(1.f, den);
    float4 bv = ((const float4*)bg_l)[r * 16 + lane];
    acc.x = acc.x * rd + bv.x; acc.y = acc.y * rd + bv.y;
    acc.z = acc.z * rd + bv.z; acc.w = acc.w * rd + bv.w;
    ((float4*)g_gat)[(size_t)d * 64 + r * 16 + lane] = acc;
}

// ---------------------------------------------------------------------------
// MLP: out = tanh([x | gat] @ W1 + b1) @ W2 + b2
// 256 threads = 8 warps; warp g owns rows g*8..g*8+7; lane cp owns cols
// cp and cp+32. Comb/hidden loads are warp-broadcast LDS (address independent
// of lane); W loads are conflict-free. 64 FFMA : 16 LDS per k-step.
// ---------------------------------------------------------------------------
__global__ void mlp_kernel(int src_sel, int write_out,
                           const float* __restrict__ xin,
                           const float* __restrict__ W1,
                           const float* __restrict__ b1,
                           const float* __restrict__ W2,
                           const float* __restrict__ b2,
                           float* __restrict__ dout, int n) {
    const float* xsrc = src_sel ? g_x2 : xin;
    float* o = write_out ? dout : g_x2;

    extern __shared__ float sm[];
    float* W1s   = sm;                    // 320*64
    float* W2s   = W1s + 320 * 64;        // 64*64
    float* combs = W2s + 64 * 64;         // 64*320
    float* hids  = combs + 64 * 320;      // 64*64

    int tid = threadIdx.x;
    int cp  = tid & 31;
    int g   = tid >> 5;
    int row0 = blockIdx.x * 64;

    // stage weights (float4)
    {
        float4* W1v = (float4*)W1s;
        const float4* W1g = (const float4*)W1;
        for (int i = tid; i < 320 * 64 / 4; i += 256) W1v[i] = W1g[i];
        float4* W2v = (float4*)W2s;
        const float4* W2g = (const float4*)W2;
        for (int i = tid; i < 64 * 64 / 4; i += 256) W2v[i] = W2g[i];
    }
    float b1c0 = b1[cp], b1c1 = b1[cp + 32];
    float b2c0 = b2[cp], b2c1 = b2[cp + 32];

    // comb tile: 64 rows x 80 float4 (16 from xsrc, 64 from g_gat)
    {
        float4* dst = (float4*)combs;
        for (int i = tid; i < 64 * 80; i += 256) {
            int row = i / 80;
            int c4  = i - row * 80;
            int grow = row0 + row;
            float4 v = make_float4(0.f, 0.f, 0.f, 0.f);
            if (grow < n) {
                if (c4 < 16) v = ((const float4*)xsrc)[(size_t)grow * 16 + c4];
                else         v = ((const float4*)g_gat)[(size_t)grow * 64 + (c4 - 16)];
            }
            dst[i] = v;
        }
    }
    __syncthreads();

    float acc[8][2];
#pragma unroll
    for (int q = 0; q < 8; q++) { acc[q][0] = 0.f; acc[q][1] = 0.f; }
    const float4* c4p = (const float4*)(combs + g * 8 * 320);
#pragma unroll 4
    for (int k4 = 0; k4 < 80; k4++) {
        float w00 = W1s[(4 * k4 + 0) * 64 + cp];
        float w01 = W1s[(4 * k4 + 1) * 64 + cp];
        float w02 = W1s[(4 * k4 + 2) * 64 + cp];
        float w03 = W1s[(4 * k4 + 3) * 64 + cp];
        float w10 = W1s[(4 * k4 + 0) * 64 + cp + 32];
        float w11 = W1s[(4 * k4 + 1) * 64 + cp + 32];
        float w12 = W1s[(4 * k4 + 2) * 64 + cp + 32];
        float w13 = W1s[(4 * k4 + 3) * 64 + cp + 32];
#pragma unroll
        for (int q = 0; q < 8; q++) {
            float4 cv = c4p[q * 80 + k4];   // warp-broadcast
            acc[q][0] += cv.x * w00 + cv.y * w01 + cv.z * w02 + cv.w * w03;
            acc[q][1] += cv.x * w10 + cv.y * w11 + cv.z * w12 + cv.w * w13;
        }
    }
#pragma unroll
    for (int q = 0; q < 8; q++) {
        hids[(g * 8 + q) * 64 + cp]      = tanhf(acc[q][0] + b1c0);
        hids[(g * 8 + q) * 64 + cp + 32] = tanhf(acc[q][1] + b1c1);
    }
    __syncthreads();

    float acc2[8][2];
#pragma unroll
    for (int q = 0; q < 8; q++) { acc2[q][0] = 0.f; acc2[q][1] = 0.f; }
    const float4* h4 = (const float4*)(hids + g * 8 * 64);
#pragma unroll
    for (int k4 = 0; k4 < 16; k4++) {
        float w00 = W2s[(4 * k4 + 0) * 64 + cp];
        float w01 = W2s[(4 * k4 + 1) * 64 + cp];
        float w02 = W2s[(4 * k4 + 2) * 64 + cp];
        float w03 = W2s[(4 * k4 + 3) * 64 + cp];
        float w10 = W2s[(4 * k4 + 0) * 64 + cp + 32];
        float w11 = W2s[(4 * k4 + 1) * 64 + cp + 32];
        float w12 = W2s[(4 * k4 + 2) * 64 + cp + 32];
        float w13 = W2s[(4 * k4 + 3) * 64 + cp + 32];
#pragma unroll
        for (int q = 0; q < 8; q++) {
            float4 hv = h4[q * 16 + k4];    // warp-broadcast
            acc2[q][0] += hv.x * w00 + hv.y * w01 + hv.z * w02 + hv.w * w03;
            acc2[q][1] += hv.x * w10 + hv.y * w11 + hv.z * w12 + hv.w * w13;
        }
    }

    int rbase = row0 + g * 8;
#pragma unroll
    for (int q = 0; q < 8; q++) {
        int row = rbase + q;
        if (row < n) {
            o[(size_t)row * 64 + cp]      = acc2[q][0] + b2c0;
            o[(size_t)row * 64 + cp + 32] = acc2[q][1] + b2c1;
        }
    }
}

// ---------------------------------------------------------------------------
extern "C" void kernel_launch(void* const* d_in, const int* in_sizes, int n_in,
                              void* d_out, int out_size) {
    const float* x_in  = (const float*)d_in[0];
    const void*  edges = d_in[1];
    const float* Wg    = (const float*)d_in[2];
    const float* a_src = (const float*)d_in[3];
    const float* a_dst = (const float*)d_in[4];
    const float* bg    = (const float*)d_in[5];
    const float* W1    = (const float*)d_in[6];
    const float* b1    = (const float*)d_in[7];
    const float* W2    = (const float*)d_in[8];
    const float* b2    = (const float*)d_in[9];

    int D  = in_sizes[2] / in_sizes[3];
    int LD = in_sizes[7];
    int L  = LD / D;
    int R  = in_sizes[3] / LD;
    int N  = in_sizes[0] / D;
    long long E = (long long)in_sizes[1] / (2 * R);

    cudaFuncSetAttribute(mlp_kernel,
                         cudaFuncAttributeMaxDynamicSharedMemorySize, 196608);

    static cudaStream_t s2 = 0;
    static cudaEvent_t evFork = 0, evJoin = 0;
    if (!s2) {
        cudaStreamCreateWithFlags(&s2, cudaStreamNonBlocking);
        cudaEventCreateWithFlags(&evFork, cudaEventDisableTiming);
        cudaEventCreateWithFlags(&evJoin, cudaEventDisableTiming);
    }

    long long tot = (long long)R * E;
    int nb_tot  = (int)((tot + 255) / 256);
    int nb_hist = (TOT + 255) / 256;
    int nb_gather = (N + 15) / 16;

    // Fork: CSR build on s2, layer-0 dense work on the main stream.
    cudaEventRecord(evFork, 0);
    cudaStreamWaitEvent(s2, evFork, 0);

    zero_hist_kernel<<<nb_hist, 256, 0, s2>>>();
    detect_kernel<<<1, 256, 0, s2>>>((const unsigned int*)edges);
    hist_kernel<<<nb_tot, 256, 0, s2>>>(edges, E, R);

    gemm_all_kernel<<<1184, 256>>>(0, x_in, Wg, N);
    wa_kernel<<<1, 256>>>(Wg, a_src, a_dst);
    alpha_kernel<<<391, 256>>>(0, x_in, N);

    scan1_kernel<<<NB1, 256, 0, s2>>>();
    scan2_kernel<<<1, 512, 0, s2>>>();
    scan3_kernel<<<nb_hist, 256, 0, s2>>>();
    scatter_kernel<<<nb_tot, 256, 0, s2>>>(E, R);

    cudaEventRecord(evJoin, s2);
    cudaStreamWaitEvent(0, evJoin, 0);

    for (int l = 0; l < L; l++) {
        int src_sel   = (l == 0) ? 0 : 1;
        int write_out = (l == L - 1) ? 1 : 0;

        if (l > 0) {
            wa_kernel<<<1, 256>>>(Wg + (size_t)l * R * D * D,
                                  a_src + (size_t)l * R * D,
                                  a_dst + (size_t)l * R * D);
            alpha_kernel<<<391, 256>>>(src_sel, x_in, N);
            gemm_all_kernel<<<1184, 256>>>(src_sel, x_in,
                                           Wg + (size_t)l * R * D * D, N);
        }
        gather_kernel<<<dim3(nb_gather, 4), 256>>>(bg + (size_t)l * R * D, N);
        mlp_kernel<<<(N + 63) / 64, 256, 196608>>>(
            src_sel, write_out, x_in,
            W1 + (size_t)l * 5 * D * D, b1 + (size_t)l * D,
            W2 + (size_t)l * D * D, b2 + (size_t)l * D,
            (float*)d_out, N);
    }
}

// round 17
// speedup vs baseline: 1.0567x; 1.0567x over previous
#include <cuda_runtime.h>
#include <cuda_fp16.h>

// ---------------------------------------------------------------------------
// SDGNN forward. N=100000, D=64, E=1e6, L=2, R=4.
// R13 config (fused gemm_all, 16-lane serial gather, dual-stream CSR overlap)
// with g_h stored in fp16: halves the gather's random h-row traffic
// (256B -> 128B per edge) and gemm's store traffic. All other math fp32.
// ---------------------------------------------------------------------------

#define MAXN 100000
#define MAXE 1000000
#define DD   64
#define TOT  (4 * MAXN)
#define NB1  ((TOT + 1023) / 1024)

__device__ __align__(16) float  g_x2[(size_t)MAXN * DD];       // inter-layer act
__device__ __align__(16) __half g_h [(size_t)4 * MAXN * DD];   // h[r] (fp16)
__device__ __align__(16) float  g_gat[(size_t)MAXN * 4 * DD];  // [row][r*64+c]
__device__ __align__(16) int2   g_e[(size_t)4 * MAXE];         // packed edges
__device__ int   g_eidx[(size_t)4 * MAXE];                     // CSR src indices
__device__ int   g_hist[TOT];
__device__ int   g_scan[TOT];
__device__ int   g_rp[TOT + 1];
__device__ int   g_cur[TOT];
__device__ int   g_bsum[NB1];
__device__ int   g_boff[NB1];
__device__ float g_as[(size_t)4 * MAXN];
__device__ float g_ad[(size_t)4 * MAXN];
__device__ float g_was[256];
__device__ float g_wad[256];
__device__ int   g_ms[4];
__device__ int   g_md[4];
__device__ int   g_is64;

// ---------------------------------------------------------------------------
__global__ void detect_kernel(const unsigned int* __restrict__ e) {
    __shared__ int any;
    if (threadIdx.x == 0) any = 0;
    __syncthreads();
    int i = 1 + 2 * threadIdx.x;
    if (i < 512 && e[i] != 0u) atomicOr(&any, 1);
    __syncthreads();
    if (threadIdx.x == 0) g_is64 = any ? 0 : 1;
}

__global__ void zero_hist_kernel() {
    int i = blockIdx.x * blockDim.x + threadIdx.x;
    if (i < TOT) g_hist[i] = 0;
}

__global__ void hist_kernel(const void* __restrict__ edges, long long E, int R) {
    long long i = (long long)blockIdx.x * blockDim.x + threadIdx.x;
    long long tot = (long long)R * E;
    if (i >= tot) return;
    int r = (int)(i / E);
    long long j = i - (long long)r * E;
    int s, d;
    if (g_is64) {
        const long long* p = (const long long*)edges;
        s = (int)p[(long long)(2 * r) * E + j];
        d = (int)p[(long long)(2 * r + 1) * E + j];
    } else {
        const int* p = (const int*)edges;
        s = p[(long long)(2 * r) * E + j];
        d = p[(long long)(2 * r + 1) * E + j];
    }
    g_e[(size_t)r * MAXE + j] = make_int2(s, d);
    atomicAdd(&g_hist[r * MAXN + d], 1);
}

// ---------------------------------------------------------------------------
__global__ void scan1_kernel() {
    __shared__ int sbuf[2][256];
    int t = threadIdx.x;
    int b = blockIdx.x;
    int base = b * 1024 + t * 4;
    int v0 = (base + 0 < TOT) ? g_hist[base + 0] : 0;
    int v1 = (base + 1 < TOT) ? g_hist[base + 1] : 0;
    int v2 = (base + 2 < TOT) ? g_hist[base + 2] : 0;
    int v3 = (base + 3 < TOT) ? g_hist[base + 3] : 0;
    int p0 = v0, p1 = p0 + v1, p2 = p1 + v2, p3 = p2 + v3;

    int cur = 0;
    sbuf[0][t] = p3;
    __syncthreads();
    for (int off = 1; off < 256; off <<= 1) {
        int v = sbuf[cur][t];
        if (t >= off) v += sbuf[cur][t - off];
        sbuf[1 - cur][t] = v;
        cur = 1 - cur;
        __syncthreads();
    }
    int incl = sbuf[cur][t];
    int offset = incl - p3;
    if (base + 0 < TOT) g_scan[base + 0] = offset + p0;
    if (base + 1 < TOT) g_scan[base + 1] = offset + p1;
    if (base + 2 < TOT) g_scan[base + 2] = offset + p2;
    if (base + 3 < TOT) g_scan[base + 3] = offset + p3;
    if (t == 255) g_bsum[b] = incl;
}

__global__ void scan2_kernel() {
    __shared__ int sbuf[2][512];
    int t = threadIdx.x;
    int v = (t < NB1) ? g_bsum[t] : 0;
    int cur = 0;
    sbuf[0][t] = v;
    __syncthreads();
    for (int off = 1; off < 512; off <<= 1) {
        int x = sbuf[cur][t];
        if (t >= off) x += sbuf[cur][t - off];
        sbuf[1 - cur][t] = x;
        cur = 1 - cur;
        __syncthreads();
    }
    if (t < NB1) g_boff[t] = sbuf[cur][t] - v;
}

__global__ void scan3_kernel() {
    int i = blockIdx.x * blockDim.x + threadIdx.x;
    if (i >= TOT) return;
    int incl = g_scan[i] + g_boff[i >> 10];
    g_rp[i + 1] = incl;
    g_cur[i] = incl - g_hist[i];
    if (i == 0) g_rp[0] = 0;
}

__global__ void scatter_kernel(long long E, int R) {
    long long i = (long long)blockIdx.x * blockDim.x + threadIdx.x;
    long long tot = (long long)R * E;
    if (i >= tot) return;
    int r = (int)(i / E);
    long long j = i - (long long)r * E;
    int2 e2 = g_e[(size_t)r * MAXE + j];
    int pos = atomicAdd(&g_cur[r * MAXN + e2.y], 1);
    g_eidx[pos] = e2.x;
}

// ---------------------------------------------------------------------------
__device__ __forceinline__ void atomic_fmax(int* addr, float v) {
    if (v >= 0.f) atomicMax(addr, __float_as_int(v));
    else          atomicMin((unsigned int*)addr, __float_as_uint(v));
}
__device__ __forceinline__ unsigned fkey(float f) {
    unsigned u = __float_as_uint(f);
    return (u & 0x80000000u) ? ~u : (u | 0x80000000u);
}
__device__ __forceinline__ float funkey(unsigned k) {
    unsigned u = (k & 0x80000000u) ? (k ^ 0x80000000u) : ~k;
    return __uint_as_float(u);
}

// ---------------------------------------------------------------------------
__global__ void wa_kernel(const float* __restrict__ Wg_l,
                          const float* __restrict__ as_l,
                          const float* __restrict__ ad_l) {
    int t = threadIdx.x;
    int rel = t >> 6, k = t & 63;
    const float* Wrow = Wg_l + (size_t)rel * DD * DD + (size_t)k * DD;
    float accs = 0.f, accd = 0.f;
#pragma unroll 8
    for (int c = 0; c < DD; c++) {
        float wv = Wrow[c];
        accs += wv * as_l[rel * DD + c];
        accd += wv * ad_l[rel * DD + c];
    }
    g_was[t] = accs;
    g_wad[t] = accd;
    if (t < 4) { g_ms[t] = 0xff800000; g_md[t] = 0xff800000; }
}

// ---------------------------------------------------------------------------
__global__ void alpha_kernel(int src_sel, const float* __restrict__ xin, int n) {
    const float* xsrc = src_sel ? g_x2 : xin;
    __shared__ float ws[512];
    __shared__ unsigned smax[8];
    int t = threadIdx.x;
    for (int i = t; i < 512; i += 256) {
        int o = i >> 6, k = i & 63;
        ws[i] = (o & 1) ? g_wad[(o >> 1) * 64 + k] : g_was[(o >> 1) * 64 + k];
    }
    if (t < 8) smax[t] = 0u;
    __syncthreads();

    unsigned lmax[8];
#pragma unroll
    for (int o = 0; o < 8; o++) lmax[o] = 0u;

    for (long long node = (long long)blockIdx.x * 256 + t; node < n;
         node += (long long)gridDim.x * 256) {
        float4 xr[16];
        const float4* xp = (const float4*)xsrc + (size_t)node * 16;
#pragma unroll
        for (int k4 = 0; k4 < 16; k4++) xr[k4] = xp[k4];
#pragma unroll
        for (int o = 0; o < 8; o++) {
            const float4* wv = (const float4*)(ws + o * 64);
            float acc = 0.f;
#pragma unroll
            for (int k4 = 0; k4 < 16; k4++) {
                float4 w4 = wv[k4];
                float4 x4 = xr[k4];
                acc += x4.x * w4.x + x4.y * w4.y + x4.z * w4.z + x4.w * w4.w;
            }
            int r = o >> 1;
            if (o & 1) g_ad[(size_t)r * MAXN + node] = acc;
            else       g_as[(size_t)r * MAXN + node] = acc;
            unsigned k = fkey(acc);
            if (k > lmax[o]) lmax[o] = k;
        }
    }
#pragma unroll
    for (int o = 0; o < 8; o++) atomicMax(&smax[o], lmax[o]);
    __syncthreads();
    if (t < 8) {
        float v = funkey(smax[t]);
        if (t & 1) atomic_fmax(&g_md[t >> 1], v);
        else       atomic_fmax(&g_ms[t >> 1], v);
    }
}

// ---------------------------------------------------------------------------
// Pure fused 4-relation GEMM: h[r] = x @ Wg[l,r], stored fp16.
// ---------------------------------------------------------------------------
__global__ void gemm_all_kernel(int src_sel, const float* __restrict__ xin,
                                const float* __restrict__ Wg_l, int n) {
    const float* xsrc = src_sel ? g_x2 : xin;
    __shared__ float4 xs[256];
    int t   = threadIdx.x;
    int col = t & 63;
    int rel = t >> 6;

    float w[DD];
    const float* Wr = Wg_l + (size_t)rel * DD * DD;
#pragma unroll
    for (int k = 0; k < DD; k++) w[k] = Wr[k * DD + col];

    for (long long base = (long long)blockIdx.x * 16; base < n;
         base += (long long)gridDim.x * 16) {
        __syncthreads();
        {
            int lr = t >> 4, lc = t & 15;
            if (base + lr < n)
                xs[t] = ((const float4*)xsrc)[(size_t)(base + lr) * 16 + lc];
        }
        __syncthreads();
        int rows = (n - base < 16) ? (int)(n - base) : 16;
        for (int q = 0; q < rows; q++) {
            float acc = 0.f;
            const float4* xv4 = xs + q * 16;
#pragma unroll
            for (int k4 = 0; k4 < 16; k4++) {
                float4 xv = xv4[k4];
                acc += xv.x * w[4 * k4 + 0] + xv.y * w[4 * k4 + 1] +
                       xv.z * w[4 * k4 + 2] + xv.w * w[4 * k4 + 3];
            }
            g_h[((size_t)rel * MAXN + base + q) * DD + col] = __float2half_rn(acc);
        }
    }
}

// ---------------------------------------------------------------------------
// CSR gather, serial per-dst loop (R13 structure), fp16 h rows:
// grid (ceil(n/16), 4); 16 lanes x 16 groups; lane loads uint2 = 4 halfs
// (cols 4*lane..4*lane+3) -> one 128B wavefront per h row.
// ---------------------------------------------------------------------------
__global__ void gather_kernel(const float* __restrict__ bg_l, int n) {
    int r    = blockIdx.y;
    int grp  = threadIdx.x >> 4;
    int lane = threadIdx.x & 15;
    int d = blockIdx.x * 16 + grp;
    if (d >= n) return;

    size_t rb = (size_t)r * MAXN;
    float mg = fmaxf(__int_as_float(g_ms[r]) + __int_as_float(g_md[r]), 0.f);
    float ad_d = g_ad[rb + d];
    const uint2* h2 = (const uint2*)g_h;   // 16 uint2 per 64-half row
    const float* asp = g_as;

    float e = asp[rb + d] + ad_d;
    e = e > 0.f ? e : 0.2f * e;
    float wv = __expf(e - mg);
    float den = wv;
    uint2 hu = h2[(rb + d) * 16 + lane];
    float2 p0 = __half22float2(*(const __half2*)&hu.x);
    float2 p1 = __half22float2(*(const __half2*)&hu.y);
    float4 acc = make_float4(p0.x * wv, p0.y * wv, p1.x * wv, p1.y * wv);

    int start = g_rp[r * MAXN + d];
    int end   = g_rp[r * MAXN + d + 1];
    for (int j = start; j < end; j++) {
        int s = g_eidx[j];
        float es = asp[rb + s] + ad_d;
        es = es > 0.f ? es : 0.2f * es;
        float ww = __expf(es - mg);
        den += ww;
        uint2 su = h2[(rb + s) * 16 + lane];
        float2 q0 = __half22float2(*(const __half2*)&su.x);
        float2 q1 = __half22float2(*(const __half2*)&su.y);
        acc.x += q0.x * ww; acc.y += q0.y * ww;
        acc.z += q1.x * ww; acc.w += q1.y * ww;
    }

    float rd = __fdividef(1.f, den);
    float4 bv = ((const float4*)bg_l)[r * 16 + lane];
    acc.x = acc.x * rd + bv.x; acc.y = acc.y * rd + bv.y;
    acc.z = acc.z * rd + bv.z; acc.w = acc.w * rd + bv.w;
    ((float4*)g_gat)[(size_t)d * 64 + r * 16 + lane] = acc;
}

// ---------------------------------------------------------------------------
// MLP (R13-proven): out = tanh([x | gat] @ W1 + b1) @ W2 + b2
// ---------------------------------------------------------------------------
__global__ void mlp_kernel(int src_sel, int write_out,
                           const float* __restrict__ xin,
                           const float* __restrict__ W1,
                           const float* __restrict__ b1,
                           const float* __restrict__ W2,
                           const float* __restrict__ b2,
                           float* __restrict__ dout, int n) {
    const float* xsrc = src_sel ? g_x2 : xin;
    float* o = write_out ? dout : g_x2;

    extern __shared__ float sm[];
    float* W1s   = sm;
    float* W2s   = W1s + 320 * 64;
    float* combs = W2s + 64 * 64;
    float* hids  = combs + 64 * 320;

    int tid = threadIdx.x;
    int col = tid & 63;
    int g   = tid >> 6;
    int row0 = blockIdx.x * 64;

    for (int i = tid; i < 320 * 64; i += 512) W1s[i] = W1[i];
    for (int i = tid; i < 64 * 64; i += 512)  W2s[i] = W2[i];
    float b1c = b1[col];
    float b2c = b2[col];

    {
        float4* dst = (float4*)combs;
        for (int i = tid; i < 64 * 80; i += 512) {
            int row = i / 80;
            int c4  = i - row * 80;
            int grow = row0 + row;
            float4 v = make_float4(0.f, 0.f, 0.f, 0.f);
            if (grow < n) {
                if (c4 < 16) v = ((const float4*)xsrc)[(size_t)grow * 16 + c4];
                else         v = ((const float4*)g_gat)[(size_t)grow * 64 + (c4 - 16)];
            }
            dst[i] = v;
        }
    }
    __syncthreads();

    float acc[8];
#pragma unroll
    for (int q = 0; q < 8; q++) acc[q] = 0.f;
    const float4* c4p = (const float4*)(combs + g * 8 * 320);
#pragma unroll 4
    for (int k4 = 0; k4 < 80; k4++) {
        float w0 = W1s[(4 * k4 + 0) * 64 + col];
        float w1 = W1s[(4 * k4 + 1) * 64 + col];
        float w2 = W1s[(4 * k4 + 2) * 64 + col];
        float w3 = W1s[(4 * k4 + 3) * 64 + col];
#pragma unroll
        for (int q = 0; q < 8; q++) {
            float4 cv = c4p[q * 80 + k4];
            acc[q] += cv.x * w0 + cv.y * w1 + cv.z * w2 + cv.w * w3;
        }
    }
#pragma unroll
    for (int q = 0; q < 8; q++)
        hids[(g * 8 + q) * 64 + col] = tanhf(acc[q] + b1c);
    __syncthreads();

    float acc2[8];
#pragma unroll
    for (int q = 0; q < 8; q++) acc2[q] = 0.f;
    const float4* h4 = (const float4*)(hids + g * 8 * 64);
#pragma unroll
    for (int k4 = 0; k4 < 16; k4++) {
        float w0 = W2s[(4 * k4 + 0) * 64 + col];
        float w1 = W2s[(4 * k4 + 1) * 64 + col];
        float w2 = W2s[(4 * k4 + 2) * 64 + col];
        float w3 = W2s[(4 * k4 + 3) * 64 + col];
#pragma unroll
        for (int q = 0; q < 8; q++) {
            float4 hv = h4[q * 16 + k4];
            acc2[q] += hv.x * w0 + hv.y * w1 + hv.z * w2 + hv.w * w3;
        }
    }

    int rbase = row0 + g * 8;
#pragma unroll
    for (int q = 0; q < 8; q++) {
        int row = rbase + q;
        if (row < n) o[(size_t)row * 64 + col] = acc2[q] + b2c;
    }
}

// ---------------------------------------------------------------------------
extern "C" void kernel_launch(void* const* d_in, const int* in_sizes, int n_in,
                              void* d_out, int out_size) {
    const float* x_in  = (const float*)d_in[0];
    const void*  edges = d_in[1];
    const float* Wg    = (const float*)d_in[2];
    const float* a_src = (const float*)d_in[3];
    const float* a_dst = (const float*)d_in[4];
    const float* bg    = (const float*)d_in[5];
    const float* W1    = (const float*)d_in[6];
    const float* b1    = (const float*)d_in[7];
    const float* W2    = (const float*)d_in[8];
    const float* b2    = (const float*)d_in[9];

    int D  = in_sizes[2] / in_sizes[3];
    int LD = in_sizes[7];
    int L  = LD / D;
    int R  = in_sizes[3] / LD;
    int N  = in_sizes[0] / D;
    long long E = (long long)in_sizes[1] / (2 * R);

    cudaFuncSetAttribute(mlp_kernel,
                         cudaFuncAttributeMaxDynamicSharedMemorySize, 196608);

    static cudaStream_t s2 = 0;
    static cudaEvent_t evFork = 0, evJoin = 0;
    if (!s2) {
        cudaStreamCreateWithFlags(&s2, cudaStreamNonBlocking);
        cudaEventCreateWithFlags(&evFork, cudaEventDisableTiming);
        cudaEventCreateWithFlags(&evJoin, cudaEventDisableTiming);
    }

    long long tot = (long long)R * E;
    int nb_tot  = (int)((tot + 255) / 256);
    int nb_hist = (TOT + 255) / 256;
    int nb_gather = (N + 15) / 16;

    // Fork: CSR build on s2, layer-0 dense work on the main stream.
    cudaEventRecord(evFork, 0);
    cudaStreamWaitEvent(s2, evFork, 0);

    zero_hist_kernel<<<nb_hist, 256, 0, s2>>>();
    detect_kernel<<<1, 256, 0, s2>>>((const unsigned int*)edges);
    hist_kernel<<<nb_tot, 256, 0, s2>>>(edges, E, R);

    gemm_all_kernel<<<1184, 256>>>(0, x_in, Wg, N);
    wa_kernel<<<1, 256>>>(Wg, a_src, a_dst);
    alpha_kernel<<<391, 256>>>(0, x_in, N);

    scan1_kernel<<<NB1, 256, 0, s2>>>();
    scan2_kernel<<<1, 512, 0, s2>>>();
    scan3_kernel<<<nb_hist, 256, 0, s2>>>();
    scatter_kernel<<<nb_tot, 256, 0, s2>>>(E, R);

    cudaEventRecord(evJoin, s2);
    cudaStreamWaitEvent(0, evJoin, 0);

    for (int l = 0; l < L; l++) {
        int src_sel   = (l == 0) ? 0 : 1;
        int write_out = (l == L - 1) ? 1 : 0;

        if (l > 0) {
            wa_kernel<<<1, 256>>>(Wg + (size_t)l * R * D * D,
                                  a_src + (size_t)l * R * D,
                                  a_dst + (size_t)l * R * D);
            alpha_kernel<<<391, 256>>>(src_sel, x_in, N);
            gemm_all_kernel<<<1184, 256>>>(src_sel, x_in,
                                           Wg + (size_t)l * R * D * D, N);
        }
        gather_kernel<<<dim3(nb_gather, 4), 256>>>(bg + (size_t)l * R * D, N);
        mlp_kernel<<<(N + 63) / 64, 512, 196608>>>(
            src_sel, write_out, x_in,
            W1 + (size_t)l * 5 * D * D, b1 + (size_t)l * D,
            W2 + (size_t)l * D * D, b2 + (size_t)l * D,
            (float*)d_out, N);
    }
}